// round 7
// baseline (speedup 1.0000x reference)
#include <cuda_runtime.h>
#include <cuda_bf16.h>
#include <cstdint>

#define FULLM 0xFFFFFFFFu

// Problem dims
#define DD 128
#define KK 1024
#define M_TOTAL 32768

// GEMM tiling
#define BM 64
#define BN 64
#define STR 136            // padded bf16 row stride (272B)
#define NCHUNK (KK/BN)     // 16
#define NTHREADS 256       // 8 warps: 2 (M) x 4 (N), warptile 32x16

// smem layout (bytes)
#define A_OFF    0
#define A_BYTES  (BM*STR*2)             // 17408
#define B_OFF    A_BYTES                // ring of 3
#define B_HALF   (BN*STR*2)             // 17408
#define NPSQ_OFF (B_OFF + 3*B_HALF)     // 69632
#define XSQ_OFF  (NPSQ_OFF + 4096)      // 73728
#define SMEM_BYTES (XSQ_OFF + 256)      // 73984 (x3 CTAs = 221952 <= 227KB)

// device scratch
__device__ __nv_bfloat16 g_pbf[KK*DD];
__device__ float g_psq[KK];
__device__ float g_npsq[KK];

__device__ __forceinline__ void cp_async16(void* sdst, const void* gsrc){
    unsigned saddr = (unsigned)__cvta_generic_to_shared(sdst);
    asm volatile("cp.async.cg.shared.global [%0], [%1], 16;\n" :: "r"(saddr), "l"(gsrc));
}
__device__ __forceinline__ void cp_commit(){ asm volatile("cp.async.commit_group;\n"); }
template<int N> __device__ __forceinline__ void cp_wait(){ asm volatile("cp.async.wait_group %0;\n"::"n"(N)); }

__device__ __forceinline__ void ldsm_x4(uint32_t&r0,uint32_t&r1,uint32_t&r2,uint32_t&r3,uint32_t saddr){
  asm volatile("ldmatrix.sync.aligned.m8n8.x4.shared.b16 {%0,%1,%2,%3}, [%4];\n"
    : "=r"(r0),"=r"(r1),"=r"(r2),"=r"(r3) : "r"(saddr));
}

__device__ __forceinline__ void mma_bf16(float c[4],
    uint32_t a0,uint32_t a1,uint32_t a2,uint32_t a3, uint32_t b0, uint32_t b1){
  asm volatile("mma.sync.aligned.m16n8k16.row.col.f32.bf16.bf16.f32 "
    "{%0,%1,%2,%3}, {%4,%5,%6,%7}, {%8,%9}, {%0,%1,%2,%3};\n"
    : "+f"(c[0]),"+f"(c[1]),"+f"(c[2]),"+f"(c[3])
    : "r"(a0),"r"(a1),"r"(a2),"r"(a3),"r"(b0),"r"(b1));
}

// sorted-descending top-4 insert of packed (value|index) floats.
__device__ __forceinline__ void ins4v(float* tv, float v){
  if (v > tv[3]){
    tv[3]=v;
    if (tv[3]>tv[2]){ float t=tv[2];tv[2]=tv[3];tv[3]=t; }
    if (tv[2]>tv[1]){ float t=tv[1];tv[1]=tv[2];tv[2]=t; }
    if (tv[1]>tv[0]){ float t=tv[0];tv[0]=tv[1];tv[1]=t; }
  }
}
__device__ __forceinline__ float packvi(float t, int col){
  return __uint_as_float((__float_as_uint(t) & 0xFFFFFC00u) | (unsigned)col);
}

// ---------------------------------------------------------------------------
// Kernel 1: prototypes -> bf16 + psq/npsq.  1 warp per prototype row.
// ---------------------------------------------------------------------------
__global__ void __launch_bounds__(128) proto_prep_kernel(const float* __restrict__ p){
  int row  = blockIdx.x*4 + (threadIdx.x>>5);
  int lane = threadIdx.x & 31;
  float4 v = reinterpret_cast<const float4*>(p + (size_t)row*DD)[lane];
  float s = v.x*v.x + v.y*v.y + v.z*v.z + v.w*v.w;
  __nv_bfloat162 b0 = __floats2bfloat162_rn(v.x, v.y);
  __nv_bfloat162 b1 = __floats2bfloat162_rn(v.z, v.w);
  __nv_bfloat162* dst = reinterpret_cast<__nv_bfloat162*>(g_pbf + (size_t)row*DD);
  dst[lane*2]   = b0;
  dst[lane*2+1] = b1;
  #pragma unroll
  for (int o=16;o;o>>=1) s += __shfl_xor_sync(FULLM, s, o);
  if (!lane){ g_psq[row] = s; g_npsq[row] = -s; }
}

// ---------------------------------------------------------------------------
// Kernel 2: fused GEMM + scores + packed top-4 + exact fixup.
// CTA: 64 rows x K=1024 in 16 chunks of 64. 8 warps (2x4), warptile 32x16.
// 3-stage cp.async ring, one __syncthreads per chunk. 3 CTAs/SM (regs<=84).
// ---------------------------------------------------------------------------
__global__ void __launch_bounds__(NTHREADS,3)
gemm_scores_kernel(const float* __restrict__ x, const float* __restrict__ p,
                   float* __restrict__ scores, float* __restrict__ matched)
{
  extern __shared__ char smem[];
  __nv_bfloat16* xs    = (__nv_bfloat16*)(smem + A_OFF);
  __nv_bfloat16* ps    = (__nv_bfloat16*)(smem + B_OFF);
  float*         npsq_s= (float*)(smem + NPSQ_OFF);
  float*         xsq_s = (float*)(smem + XSQ_OFF);

  const int tid  = threadIdx.x;
  const int lane = tid & 31;
  const int wid  = tid >> 5;
  const int wm   = wid >> 2;   // 0..1
  const int wn   = wid & 3;    // 0..3
  const int blockRow = blockIdx.x * BM;

  const unsigned smem_u32 = (unsigned)__cvta_generic_to_shared(smem);
  const unsigned xs_u32 = smem_u32 + A_OFF;
  const unsigned ps_u32 = smem_u32 + B_OFF;

#define LOADP(c_, b_) do {                                            \
    const __nv_bfloat16* _src = g_pbf + (size_t)(c_)*BN*DD;           \
    __nv_bfloat16* _dst = ps + (b_)*BN*STR;                           \
    _Pragma("unroll")                                                 \
    for (int _t=0;_t<4;_t++){                                         \
      int _id = tid + _t*NTHREADS;                                    \
      int _r = _id >> 4, _cp = _id & 15;                              \
      cp_async16(_dst + _r*STR + _cp*8, _src + _r*DD + _cp*8);        \
    }                                                                 \
    cp_commit();                                                      \
  } while(0)

  LOADP(0, 0);
  LOADP(1, 1);

  // negated psq -> smem (once)
  #pragma unroll
  for (int k=0;k<4;k++) npsq_s[tid + k*NTHREADS] = g_npsq[tid + k*NTHREADS];

  // x tile fp32 -> bf16 smem + row sumsq (4 threads / row)
  {
    int r = tid >> 2;          // 0..63
    int q = tid & 3;
    const float4* src = (const float4*)(x + (size_t)(blockRow + r)*DD + q*32);
    float s = 0.f;
    #pragma unroll
    for (int i=0;i<8;i++){
      float4 v = src[i];
      s += v.x*v.x + v.y*v.y + v.z*v.z + v.w*v.w;
      __nv_bfloat162 b0 = __floats2bfloat162_rn(v.x, v.y);
      __nv_bfloat162 b1 = __floats2bfloat162_rn(v.z, v.w);
      *(__nv_bfloat162*)&xs[r*STR + q*32 + i*4]     = b0;
      *(__nv_bfloat162*)&xs[r*STR + q*32 + i*4 + 2] = b1;
    }
    s += __shfl_xor_sync(FULLM, s, 1);
    s += __shfl_xor_sync(FULLM, s, 2);
    if (!q) xsq_s[r] = s;
  }
  __syncthreads();

  // per-thread row sumsq (4 rows per thread: mf2 x h2)
  float xq[4];
  #pragma unroll
  for (int mf=0;mf<2;mf++)
    #pragma unroll
    for (int h=0;h<2;h++)
      xq[mf*2+h] = xsq_s[wm*32 + mf*16 + h*8 + (lane>>2)];

  // ldmatrix base addresses (bytes)
  unsigned aAddr[2];
  #pragma unroll
  for (int mf=0;mf<2;mf++)
    aAddr[mf] = xs_u32 + ((wm*32 + mf*16 + (lane&15))*STR + (lane>>4)*8)*2;
  const unsigned bOff = ((wn*16 + (lane>>4)*8 + (lane&7))*STR + ((lane>>3)&1)*8)*2;

  // packed top-4 per thread per row
  float tv[4][4];
  #pragma unroll
  for (int r=0;r<4;r++)
    #pragma unroll
    for (int j=0;j<4;j++) tv[r][j] = -1e30f;

  int buf = 0;
  for (int chunk=0; chunk<NCHUNK; chunk++){
    if (chunk < NCHUNK-1) cp_wait<1>(); else cp_wait<0>();
    __syncthreads();
    // prefetch chunk+2 into the buffer last read at iteration chunk-1
    if (chunk+2 < NCHUNK){
      int nb = buf+2; if (nb >= 3) nb -= 3;
      LOADP(chunk+2, nb);
    }

    const unsigned bBase = ps_u32 + buf*B_HALF + bOff;

    float acc[2][2][4];
    #pragma unroll
    for (int mf=0;mf<2;mf++)
      #pragma unroll
      for (int nf=0;nf<2;nf++)
        #pragma unroll
        for (int q=0;q<4;q++) acc[mf][nf][q] = 0.f;

    #pragma unroll
    for (int kt=0;kt<8;kt++){
      uint32_t a[2][4], b[4];
      ldsm_x4(b[0],b[1],b[2],b[3], bBase + kt*32);
      #pragma unroll
      for (int mf=0;mf<2;mf++)
        ldsm_x4(a[mf][0],a[mf][1],a[mf][2],a[mf][3], aAddr[mf] + kt*32);
      #pragma unroll
      for (int mf=0;mf<2;mf++){
        mma_bf16(acc[mf][0], a[mf][0],a[mf][1],a[mf][2],a[mf][3], b[0], b[1]);
        mma_bf16(acc[mf][1], a[mf][0],a[mf][1],a[mf][2],a[mf][3], b[2], b[3]);
      }
    }

    // epilogue: scores = (2xp - psq) - xsq ; track packed top-4 of (2xp - psq)
    const int colBase = chunk*BN + wn*16;
    const int cl2 = (lane&3)*2;
    float npq[4];
    {
      float2 v0 = *(const float2*)&npsq_s[colBase + cl2];
      float2 v1 = *(const float2*)&npsq_s[colBase + 8 + cl2];
      npq[0]=v0.x; npq[1]=v0.y; npq[2]=v1.x; npq[3]=v1.y;
    }
    #pragma unroll
    for (int mf=0;mf<2;mf++){
      #pragma unroll
      for (int h=0;h<2;h++){
        const int rl   = mf*2 + h;
        const int grow = blockRow + wm*32 + mf*16 + h*8 + (lane>>2);
        const float xqv = xq[rl];
        float* srow = scores + (size_t)grow*KK;
        #pragma unroll
        for (int nf=0;nf<2;nf++){
          const int col = colBase + nf*8 + cl2;
          float t0 = fmaf(2.f, acc[mf][nf][h*2+0], npq[2*nf]);
          float t1 = fmaf(2.f, acc[mf][nf][h*2+1], npq[2*nf+1]);
          float2 o; o.x = t0 - xqv; o.y = t1 - xqv;
          *(float2*)(srow + col) = o;
          ins4v(tv[rl], packvi(t0, col));
          ins4v(tv[rl], packvi(t1, col+1));
        }
      }
    }
    buf++; if (buf >= 3) buf -= 3;
  }
  __syncthreads();

  // ---- per-row candidate merge (64 packed cands/row -> top 4) ----
  float* mv = (float*)(smem + A_OFF);              // [64][64] = 16KB
  int4*  c4 = (int4*) (smem + A_OFF + 64*64*4);    // [64]
  #pragma unroll
  for (int mf=0;mf<2;mf++){
    #pragma unroll
    for (int h=0;h<2;h++){
      int r = wm*32 + mf*16 + h*8 + (lane>>2);
      int base = r*64 + wn*16 + (lane&3)*4;
      #pragma unroll
      for (int j=0;j<4;j++) mv[base+j] = tv[mf*2+h][j];
    }
  }
  __syncthreads();
  if (tid < BM){
    float bv[4] = {-1e30f,-1e30f,-1e30f,-1e30f};
    for (int s=0;s<64;s++) ins4v(bv, mv[tid*64+s]);
    int4 o;
    o.x = (int)(__float_as_uint(bv[0]) & 1023u);
    o.y = (int)(__float_as_uint(bv[1]) & 1023u);
    o.z = (int)(__float_as_uint(bv[2]) & 1023u);
    o.w = (int)(__float_as_uint(bv[3]) & 1023u);
    c4[tid] = o;
  }
  __syncthreads();

  // ---- exact fp32 fixup: 8 warps x 8 rows, 4 candidates each ----
  #pragma unroll
  for (int rr=0; rr<8; rr++){
    const int r    = wid*8 + rr;
    const int grow = blockRow + r;
    float4 xv = reinterpret_cast<const float4*>(x + (size_t)grow*DD)[lane];
    const float xqe = xsq_s[r];
    int4 cd = c4[r];
    int cands[4] = {cd.x, cd.y, cd.z, cd.w};
    float bt = 1e30f; int bi = 0x7fffffff;
    #pragma unroll
    for (int j=0;j<4;j++){
      int ci = cands[j];
      float4 pv = reinterpret_cast<const float4*>(p + (size_t)ci*DD)[lane];
      float d = xv.x*pv.x + xv.y*pv.y + xv.z*pv.z + xv.w*pv.w;
      #pragma unroll
      for (int o=16;o;o>>=1) d += __shfl_xor_sync(FULLM, d, o);
      float t = (xqe + g_psq[ci]) - 2.f*d;   // minimize
      if (t < bt || (t == bt && ci < bi)){ bt = t; bi = ci; }
    }
    float4 pv = reinterpret_cast<const float4*>(p + (size_t)bi*DD)[lane];
    reinterpret_cast<float4*>(matched + (size_t)grow*DD)[lane] = pv;
  }
#undef LOADP
}

// ---------------------------------------------------------------------------
extern "C" void kernel_launch(void* const* d_in, const int* in_sizes, int n_in,
                              void* d_out, int out_size)
{
  const float* x = (const float*)d_in[0];   // [8,4096,128] f32
  const float* p = (const float*)d_in[1];   // [1024,128]   f32
  float* matched = (float*)d_out;                                  // [32768,128]
  float* scores  = (float*)d_out + (size_t)M_TOTAL*DD;             // [32768,1024]

  cudaFuncSetAttribute(gemm_scores_kernel,
                       cudaFuncAttributeMaxDynamicSharedMemorySize, SMEM_BYTES);

  proto_prep_kernel<<<KK/4, 128>>>(p);
  gemm_scores_kernel<<<M_TOTAL/BM, NTHREADS, SMEM_BYTES>>>(x, p, scores, matched);
}

// round 8
// speedup vs baseline: 1.2029x; 1.2029x over previous
#include <cuda_runtime.h>
#include <cuda_bf16.h>
#include <cstdint>

#define FULLM 0xFFFFFFFFu

// Problem dims
#define DD 128
#define KK 1024
#define M_TOTAL 32768

// GEMM tiling
#define BM 64
#define BN 64
#define STR 136            // padded bf16 row stride (272B)
#define NCHUNK (KK/BN)     // 16
#define NTHREADS 256       // 8 warps: 2 (M) x 4 (N), warptile 32x16

// smem layout (bytes)
#define A_OFF    0
#define A_BYTES  (BM*STR*2)             // 17408
#define B_OFF    A_BYTES                // ring of 3
#define B_HALF   (BN*STR*2)             // 17408
#define NPSQ_OFF (B_OFF + 3*B_HALF)     // 69632
#define XSQ_OFF  (NPSQ_OFF + 4096)      // 73728
#define MBAR_OFF (XSQ_OFF + 256)        // 73984
#define SMEM_BYTES (MBAR_OFF + 64)      // 74048 (x2 CTAs fits 227KB)

// device scratch: P tiles pre-laid-out as padded [64][STR] bf16 smem images
__device__ __align__(16) unsigned char g_pimg[NCHUNK*B_HALF];
__device__ float g_psq[KK];
__device__ float g_npsq[KK];

__device__ __forceinline__ void ldsm_x4(uint32_t&r0,uint32_t&r1,uint32_t&r2,uint32_t&r3,uint32_t saddr){
  asm volatile("ldmatrix.sync.aligned.m8n8.x4.shared.b16 {%0,%1,%2,%3}, [%4];\n"
    : "=r"(r0),"=r"(r1),"=r"(r2),"=r"(r3) : "r"(saddr));
}

__device__ __forceinline__ void mma_bf16(float c[4],
    uint32_t a0,uint32_t a1,uint32_t a2,uint32_t a3, uint32_t b0, uint32_t b1){
  asm volatile("mma.sync.aligned.m16n8k16.row.col.f32.bf16.bf16.f32 "
    "{%0,%1,%2,%3}, {%4,%5,%6,%7}, {%8,%9}, {%0,%1,%2,%3};\n"
    : "+f"(c[0]),"+f"(c[1]),"+f"(c[2]),"+f"(c[3])
    : "r"(a0),"r"(a1),"r"(a2),"r"(a3),"r"(b0),"r"(b1));
}

__device__ __forceinline__ void mbar_init(unsigned addr, unsigned cnt){
  asm volatile("mbarrier.init.shared.b64 [%0], %1;" :: "r"(addr), "r"(cnt) : "memory");
}
__device__ __forceinline__ void mbar_expect_tx(unsigned addr, unsigned bytes){
  asm volatile("mbarrier.arrive.expect_tx.shared.b64 _, [%0], %1;"
               :: "r"(addr), "r"(bytes) : "memory");
}
__device__ __forceinline__ void bulk_g2s(unsigned sdst, const void* gsrc, unsigned bytes, unsigned mbar){
  asm volatile("cp.async.bulk.shared::cta.global.mbarrier::complete_tx::bytes [%0], [%1], %2, [%3];"
               :: "r"(sdst), "l"(gsrc), "r"(bytes), "r"(mbar) : "memory");
}
__device__ __forceinline__ void mbar_wait(unsigned addr, unsigned parity){
  unsigned done;
  asm volatile("{\n\t.reg .pred p;\n\t"
    "mbarrier.try_wait.parity.acquire.cta.shared::cta.b64 p, [%1], %2;\n\t"
    "selp.b32 %0, 1, 0, p;\n\t}" : "=r"(done) : "r"(addr), "r"(parity) : "memory");
  while (!done){
    asm volatile("{\n\t.reg .pred p;\n\t"
      "mbarrier.try_wait.parity.acquire.cta.shared::cta.b64 p, [%1], %2, 0x989680;\n\t"
      "selp.b32 %0, 1, 0, p;\n\t}" : "=r"(done) : "r"(addr), "r"(parity) : "memory");
  }
}

// sorted-descending top-4 insert of packed (value|index) floats.
__device__ __forceinline__ void ins4v(float* tv, float v){
  if (v > tv[3]){
    tv[3]=v;
    if (tv[3]>tv[2]){ float t=tv[2];tv[2]=tv[3];tv[3]=t; }
    if (tv[2]>tv[1]){ float t=tv[1];tv[1]=tv[2];tv[2]=t; }
    if (tv[1]>tv[0]){ float t=tv[0];tv[0]=tv[1];tv[1]=t; }
  }
}
__device__ __forceinline__ float packvi(float t, int col){
  return __uint_as_float((__float_as_uint(t) & 0xFFFFFC00u) | (unsigned)col);
}

// ---------------------------------------------------------------------------
// Kernel 1: prototypes -> padded bf16 tile image + psq/npsq.  1 warp / row.
// Image: chunk = row/64, local r = row%64, layout [r][STR] bf16.
// ---------------------------------------------------------------------------
__global__ void __launch_bounds__(128) proto_prep_kernel(const float* __restrict__ p){
  int row  = blockIdx.x*4 + (threadIdx.x>>5);
  int lane = threadIdx.x & 31;
  float4 v = reinterpret_cast<const float4*>(p + (size_t)row*DD)[lane];
  float s = v.x*v.x + v.y*v.y + v.z*v.z + v.w*v.w;
  __nv_bfloat162 b0 = __floats2bfloat162_rn(v.x, v.y);
  __nv_bfloat162 b1 = __floats2bfloat162_rn(v.z, v.w);
  uint2 w; w.x = *(uint32_t*)&b0; w.y = *(uint32_t*)&b1;
  int chunk = row >> 6, r = row & 63;
  *(uint2*)(g_pimg + (size_t)chunk*B_HALF + r*(STR*2) + lane*8) = w;
  #pragma unroll
  for (int o=16;o;o>>=1) s += __shfl_xor_sync(FULLM, s, o);
  if (!lane){ g_psq[row] = s; g_npsq[row] = -s; }
}

// ---------------------------------------------------------------------------
// Kernel 2: fused GEMM (A-in-registers) + scores + packed top-4 + exact fixup.
// CTA: 64 rows x K=1024 in 16 chunks of 64. 8 warps (2x4), warptile 32x16.
// B fed by cp.async.bulk (1 op/chunk) into a 3-slot mbarrier ring. 2 CTAs/SM.
// ---------------------------------------------------------------------------
__global__ void __launch_bounds__(NTHREADS,2)
gemm_scores_kernel(const float* __restrict__ x, const float* __restrict__ p,
                   float* __restrict__ scores, float* __restrict__ matched)
{
  extern __shared__ char smem[];
  __nv_bfloat16* xs    = (__nv_bfloat16*)(smem + A_OFF);
  float*         npsq_s= (float*)(smem + NPSQ_OFF);
  float*         xsq_s = (float*)(smem + XSQ_OFF);

  const int tid  = threadIdx.x;
  const int lane = tid & 31;
  const int wid  = tid >> 5;
  const int wm   = wid >> 2;   // 0..1
  const int wn   = wid & 3;    // 0..3
  const int blockRow = blockIdx.x * BM;

  const unsigned smem_u32 = (unsigned)__cvta_generic_to_shared(smem);
  const unsigned xs_u32 = smem_u32 + A_OFF;
  const unsigned ps_u32 = smem_u32 + B_OFF;
  const unsigned mb_u32 = smem_u32 + MBAR_OFF;

  // init mbarriers + kick off first two bulk loads (single thread)
  if (tid == 0){
    mbar_init(mb_u32,      1);
    mbar_init(mb_u32 + 8,  1);
    mbar_init(mb_u32 + 16, 1);
    mbar_expect_tx(mb_u32, B_HALF);
    bulk_g2s(ps_u32, g_pimg, B_HALF, mb_u32);
    mbar_expect_tx(mb_u32 + 8, B_HALF);
    bulk_g2s(ps_u32 + B_HALF, g_pimg + B_HALF, B_HALF, mb_u32 + 8);
  }

  // negated psq -> smem (once)
  #pragma unroll
  for (int k=0;k<4;k++) npsq_s[tid + k*NTHREADS] = g_npsq[tid + k*NTHREADS];

  // x tile fp32 -> bf16 smem + row sumsq (4 threads / row)
  {
    int r = tid >> 2;          // 0..63
    int q = tid & 3;
    const float4* src = (const float4*)(x + (size_t)(blockRow + r)*DD + q*32);
    float s = 0.f;
    #pragma unroll
    for (int i=0;i<8;i++){
      float4 v = src[i];
      s += v.x*v.x + v.y*v.y + v.z*v.z + v.w*v.w;
      __nv_bfloat162 b0 = __floats2bfloat162_rn(v.x, v.y);
      __nv_bfloat162 b1 = __floats2bfloat162_rn(v.z, v.w);
      *(__nv_bfloat162*)&xs[r*STR + q*32 + i*4]     = b0;
      *(__nv_bfloat162*)&xs[r*STR + q*32 + i*4 + 2] = b1;
    }
    s += __shfl_xor_sync(FULLM, s, 1);
    s += __shfl_xor_sync(FULLM, s, 2);
    if (!q) xsq_s[r] = s;
  }
  __syncthreads();

  // A fragments for all of K: a[8 ksteps][2 mf][4 regs] = 64 regs, loaded once.
  uint32_t afr[8][2][4];
  {
    unsigned aAddr[2];
    #pragma unroll
    for (int mf=0;mf<2;mf++)
      aAddr[mf] = xs_u32 + ((wm*32 + mf*16 + (lane&15))*STR + (lane>>4)*8)*2;
    #pragma unroll
    for (int kt=0;kt<8;kt++)
      #pragma unroll
      for (int mf=0;mf<2;mf++)
        ldsm_x4(afr[kt][mf][0],afr[kt][mf][1],afr[kt][mf][2],afr[kt][mf][3],
                aAddr[mf] + kt*32);
  }

  // per-thread row sumsq (4 rows per thread: mf2 x h2)
  float xq[4];
  #pragma unroll
  for (int mf=0;mf<2;mf++)
    #pragma unroll
    for (int h=0;h<2;h++)
      xq[mf*2+h] = xsq_s[wm*32 + mf*16 + h*8 + (lane>>2)];

  // B ldmatrix offset within a ring slot
  const unsigned bOff = ((wn*16 + (lane>>4)*8 + (lane&7))*STR + ((lane>>3)&1)*8)*2;

  // packed top-4 per thread per row
  float tv[4][4];
  #pragma unroll
  for (int r=0;r<4;r++)
    #pragma unroll
    for (int j=0;j<4;j++) tv[r][j] = -1e30f;

  int slot = 0;
  for (int chunk=0; chunk<NCHUNK; chunk++){
    // data ready for this slot?
    mbar_wait(mb_u32 + slot*8, (chunk/3)&1);
    __syncthreads();   // also proves all warps finished reading slot (chunk+2)%3
    if (chunk+2 < NCHUNK && tid == 0){
      int ns = slot+2; if (ns >= 3) ns -= 3;
      unsigned mb = mb_u32 + ns*8;
      mbar_expect_tx(mb, B_HALF);
      bulk_g2s(ps_u32 + ns*B_HALF, g_pimg + (size_t)(chunk+2)*B_HALF, B_HALF, mb);
    }

    const unsigned bBase = ps_u32 + slot*B_HALF + bOff;

    float acc[2][2][4];
    #pragma unroll
    for (int mf=0;mf<2;mf++)
      #pragma unroll
      for (int nf=0;nf<2;nf++)
        #pragma unroll
        for (int q=0;q<4;q++) acc[mf][nf][q] = 0.f;

    #pragma unroll
    for (int kt=0;kt<8;kt++){
      uint32_t b[4];
      ldsm_x4(b[0],b[1],b[2],b[3], bBase + kt*32);
      #pragma unroll
      for (int mf=0;mf<2;mf++){
        mma_bf16(acc[mf][0], afr[kt][mf][0],afr[kt][mf][1],afr[kt][mf][2],afr[kt][mf][3], b[0], b[1]);
        mma_bf16(acc[mf][1], afr[kt][mf][0],afr[kt][mf][1],afr[kt][mf][2],afr[kt][mf][3], b[2], b[3]);
      }
    }

    // epilogue: scores = (2xp - psq) - xsq ; track packed top-4 of (2xp - psq)
    const int colBase = chunk*BN + wn*16;
    const int cl2 = (lane&3)*2;
    float npq[4];
    {
      float2 v0 = *(const float2*)&npsq_s[colBase + cl2];
      float2 v1 = *(const float2*)&npsq_s[colBase + 8 + cl2];
      npq[0]=v0.x; npq[1]=v0.y; npq[2]=v1.x; npq[3]=v1.y;
    }
    #pragma unroll
    for (int mf=0;mf<2;mf++){
      #pragma unroll
      for (int h=0;h<2;h++){
        const int rl   = mf*2 + h;
        const int grow = blockRow + wm*32 + mf*16 + h*8 + (lane>>2);
        const float xqv = xq[rl];
        float* srow = scores + (size_t)grow*KK;
        #pragma unroll
        for (int nf=0;nf<2;nf++){
          const int col = colBase + nf*8 + cl2;
          float t0 = fmaf(2.f, acc[mf][nf][h*2+0], npq[2*nf]);
          float t1 = fmaf(2.f, acc[mf][nf][h*2+1], npq[2*nf+1]);
          float2 o; o.x = t0 - xqv; o.y = t1 - xqv;
          *(float2*)(srow + col) = o;
          ins4v(tv[rl], packvi(t0, col));
          ins4v(tv[rl], packvi(t1, col+1));
        }
      }
    }
    slot++; if (slot >= 3) slot -= 3;
  }
  __syncthreads();

  // ---- per-row candidate merge (64 packed cands/row -> top 4) ----
  float* mv = (float*)(smem + A_OFF);              // [64][64] = 16KB
  int4*  c4 = (int4*) (smem + A_OFF + 64*64*4);    // [64]
  #pragma unroll
  for (int mf=0;mf<2;mf++){
    #pragma unroll
    for (int h=0;h<2;h++){
      int r = wm*32 + mf*16 + h*8 + (lane>>2);
      int base = r*64 + wn*16 + (lane&3)*4;
      #pragma unroll
      for (int j=0;j<4;j++) mv[base+j] = tv[mf*2+h][j];
    }
  }
  __syncthreads();
  if (tid < BM){
    float bv[4] = {-1e30f,-1e30f,-1e30f,-1e30f};
    for (int s=0;s<64;s++) ins4v(bv, mv[tid*64+s]);
    int4 o;
    o.x = (int)(__float_as_uint(bv[0]) & 1023u);
    o.y = (int)(__float_as_uint(bv[1]) & 1023u);
    o.z = (int)(__float_as_uint(bv[2]) & 1023u);
    o.w = (int)(__float_as_uint(bv[3]) & 1023u);
    c4[tid] = o;
  }
  __syncthreads();

  // ---- exact fp32 fixup: 8 warps x 8 rows, 4 candidates each ----
  #pragma unroll
  for (int rr=0; rr<8; rr++){
    const int r    = wid*8 + rr;
    const int grow = blockRow + r;
    float4 xv = reinterpret_cast<const float4*>(x + (size_t)grow*DD)[lane];
    const float xqe = xsq_s[r];
    int4 cd = c4[r];
    int cands[4] = {cd.x, cd.y, cd.z, cd.w};
    float bt = 1e30f; int bi = 0x7fffffff;
    #pragma unroll
    for (int j=0;j<4;j++){
      int ci = cands[j];
      float4 pv = reinterpret_cast<const float4*>(p + (size_t)ci*DD)[lane];
      float d = xv.x*pv.x + xv.y*pv.y + xv.z*pv.z + xv.w*pv.w;
      #pragma unroll
      for (int o=16;o;o>>=1) d += __shfl_xor_sync(FULLM, d, o);
      float t = (xqe + g_psq[ci]) - 2.f*d;   // minimize
      if (t < bt || (t == bt && ci < bi)){ bt = t; bi = ci; }
    }
    float4 pv = reinterpret_cast<const float4*>(p + (size_t)bi*DD)[lane];
    reinterpret_cast<float4*>(matched + (size_t)grow*DD)[lane] = pv;
  }
}

// ---------------------------------------------------------------------------
extern "C" void kernel_launch(void* const* d_in, const int* in_sizes, int n_in,
                              void* d_out, int out_size)
{
  const float* x = (const float*)d_in[0];   // [8,4096,128] f32
  const float* p = (const float*)d_in[1];   // [1024,128]   f32
  float* matched = (float*)d_out;                                  // [32768,128]
  float* scores  = (float*)d_out + (size_t)M_TOTAL*DD;             // [32768,1024]

  cudaFuncSetAttribute(gemm_scores_kernel,
                       cudaFuncAttributeMaxDynamicSharedMemorySize, SMEM_BYTES);

  proto_prep_kernel<<<KK/4, 128>>>(p);
  gemm_scores_kernel<<<M_TOTAL/BM, NTHREADS, SMEM_BYTES>>>(x, p, scores, matched);
}

// round 9
// speedup vs baseline: 1.5325x; 1.2740x over previous
#include <cuda_runtime.h>
#include <cuda_bf16.h>
#include <cstdint>

#define FULLM 0xFFFFFFFFu

// Problem dims
#define DD 128
#define KK 1024
#define M_TOTAL 32768

// GEMM tiling
#define BM 64
#define BN 64
#define STR 136            // padded bf16 row stride (272B)
#define NCHUNK (KK/BN)     // 16
#define NTHREADS 256       // 8 warps: 2 (M) x 4 (N), warptile 32x16

// smem layout (bytes)
#define A_OFF    0
#define A_BYTES  (BM*STR*2)             // 17408
#define B_OFF    A_BYTES                // ring of 3
#define B_HALF   (BN*STR*2)             // 17408
#define NPSQ_OFF (B_OFF + 3*B_HALF)     // 69632
#define XSQ_OFF  (NPSQ_OFF + 4096)      // 73728
#define MBAR_OFF (XSQ_OFF + 256)        // 73984
#define SMEM_BYTES (MBAR_OFF + 64)      // 74048 (x2 CTAs fits 227KB)

// device scratch: P tiles pre-laid-out as padded [64][STR] bf16 smem images
__device__ __align__(16) unsigned char g_pimg[NCHUNK*B_HALF];
__device__ float g_psq[KK];
__device__ float g_npsq[KK];

__device__ __forceinline__ void ldsm_x4(uint32_t&r0,uint32_t&r1,uint32_t&r2,uint32_t&r3,uint32_t saddr){
  asm volatile("ldmatrix.sync.aligned.m8n8.x4.shared.b16 {%0,%1,%2,%3}, [%4];\n"
    : "=r"(r0),"=r"(r1),"=r"(r2),"=r"(r3) : "r"(saddr));
}

__device__ __forceinline__ void mma_bf16(float c[4],
    uint32_t a0,uint32_t a1,uint32_t a2,uint32_t a3, uint32_t b0, uint32_t b1){
  asm volatile("mma.sync.aligned.m16n8k16.row.col.f32.bf16.bf16.f32 "
    "{%0,%1,%2,%3}, {%4,%5,%6,%7}, {%8,%9}, {%0,%1,%2,%3};\n"
    : "+f"(c[0]),"+f"(c[1]),"+f"(c[2]),"+f"(c[3])
    : "r"(a0),"r"(a1),"r"(a2),"r"(a3),"r"(b0),"r"(b1));
}

__device__ __forceinline__ void mbar_init(unsigned addr, unsigned cnt){
  asm volatile("mbarrier.init.shared.b64 [%0], %1;" :: "r"(addr), "r"(cnt) : "memory");
}
__device__ __forceinline__ void mbar_expect_tx(unsigned addr, unsigned bytes){
  asm volatile("mbarrier.arrive.expect_tx.shared.b64 _, [%0], %1;"
               :: "r"(addr), "r"(bytes) : "memory");
}
__device__ __forceinline__ void bulk_g2s(unsigned sdst, const void* gsrc, unsigned bytes, unsigned mbar){
  asm volatile("cp.async.bulk.shared::cta.global.mbarrier::complete_tx::bytes [%0], [%1], %2, [%3];"
               :: "r"(sdst), "l"(gsrc), "r"(bytes), "r"(mbar) : "memory");
}
__device__ __forceinline__ void mbar_wait(unsigned addr, unsigned parity){
  unsigned done;
  asm volatile("{\n\t.reg .pred p;\n\t"
    "mbarrier.try_wait.parity.acquire.cta.shared::cta.b64 p, [%1], %2;\n\t"
    "selp.b32 %0, 1, 0, p;\n\t}" : "=r"(done) : "r"(addr), "r"(parity) : "memory");
  while (!done){
    asm volatile("{\n\t.reg .pred p;\n\t"
      "mbarrier.try_wait.parity.acquire.cta.shared::cta.b64 p, [%1], %2, 0x989680;\n\t"
      "selp.b32 %0, 1, 0, p;\n\t}" : "=r"(done) : "r"(addr), "r"(parity) : "memory");
  }
}

// branchless sorted-descending top-4 insert: 8 FMNMX, no BSSY/BSYNC.
__device__ __forceinline__ void ins4b(float* tv, float v){
  float m3 = fmaxf(tv[3], v);
  float m2 = fmaxf(tv[2], m3); tv[3] = fminf(tv[2], m3);
  float m1 = fmaxf(tv[1], m2); tv[2] = fminf(tv[1], m2);
  float m0 = fmaxf(tv[0], m1); tv[1] = fminf(tv[0], m1); tv[0] = m0;
}
// pack score value with 10-bit column index in low mantissa bits (1 LOP3)
__device__ __forceinline__ float packvi(float t, int col){
  return __uint_as_float((__float_as_uint(t) & 0xFFFFFC00u) | (unsigned)col);
}

// ---------------------------------------------------------------------------
// Kernel 1: prototypes -> padded bf16 tile image + psq/npsq.  1 warp / row.
// ---------------------------------------------------------------------------
__global__ void __launch_bounds__(128) proto_prep_kernel(const float* __restrict__ p){
  int row  = blockIdx.x*4 + (threadIdx.x>>5);
  int lane = threadIdx.x & 31;
  float4 v = reinterpret_cast<const float4*>(p + (size_t)row*DD)[lane];
  float s = v.x*v.x + v.y*v.y + v.z*v.z + v.w*v.w;
  __nv_bfloat162 b0 = __floats2bfloat162_rn(v.x, v.y);
  __nv_bfloat162 b1 = __floats2bfloat162_rn(v.z, v.w);
  uint2 w; w.x = *(uint32_t*)&b0; w.y = *(uint32_t*)&b1;
  int chunk = row >> 6, r = row & 63;
  *(uint2*)(g_pimg + (size_t)chunk*B_HALF + r*(STR*2) + lane*8) = w;
  #pragma unroll
  for (int o=16;o;o>>=1) s += __shfl_xor_sync(FULLM, s, o);
  if (!lane){ g_psq[row] = s; g_npsq[row] = -s; }
}

// ---------------------------------------------------------------------------
// Kernel 2: fused GEMM (A-in-registers) + scores + branchless top-4 + fixup.
// CTA: 64 rows x K=1024 in 16 chunks of 64. 8 warps (2x4), warptile 32x16.
// B fed by cp.async.bulk (1 op/chunk) into a 3-slot mbarrier ring. 2 CTAs/SM.
// ---------------------------------------------------------------------------
__global__ void __launch_bounds__(NTHREADS,2)
gemm_scores_kernel(const float* __restrict__ x, const float* __restrict__ p,
                   float* __restrict__ scores, float* __restrict__ matched)
{
  extern __shared__ char smem[];
  __nv_bfloat16* xs    = (__nv_bfloat16*)(smem + A_OFF);
  float*         npsq_s= (float*)(smem + NPSQ_OFF);
  float*         xsq_s = (float*)(smem + XSQ_OFF);

  const int tid  = threadIdx.x;
  const int lane = tid & 31;
  const int wid  = tid >> 5;
  const int wm   = wid >> 2;   // 0..1
  const int wn   = wid & 3;    // 0..3
  const int blockRow = blockIdx.x * BM;

  const unsigned smem_u32 = (unsigned)__cvta_generic_to_shared(smem);
  const unsigned xs_u32 = smem_u32 + A_OFF;
  const unsigned ps_u32 = smem_u32 + B_OFF;
  const unsigned mb_u32 = smem_u32 + MBAR_OFF;

  // init mbarriers + kick off first two bulk loads (single thread)
  if (tid == 0){
    mbar_init(mb_u32,      1);
    mbar_init(mb_u32 + 8,  1);
    mbar_init(mb_u32 + 16, 1);
    mbar_expect_tx(mb_u32, B_HALF);
    bulk_g2s(ps_u32, g_pimg, B_HALF, mb_u32);
    mbar_expect_tx(mb_u32 + 8, B_HALF);
    bulk_g2s(ps_u32 + B_HALF, g_pimg + B_HALF, B_HALF, mb_u32 + 8);
  }

  // negated psq -> smem (once)
  #pragma unroll
  for (int k=0;k<4;k++) npsq_s[tid + k*NTHREADS] = g_npsq[tid + k*NTHREADS];

  // x tile fp32 -> bf16 smem + row sumsq (4 threads / row)
  {
    int r = tid >> 2;          // 0..63
    int q = tid & 3;
    const float4* src = (const float4*)(x + (size_t)(blockRow + r)*DD + q*32);
    float s = 0.f;
    #pragma unroll
    for (int i=0;i<8;i++){
      float4 v = src[i];
      s += v.x*v.x + v.y*v.y + v.z*v.z + v.w*v.w;
      __nv_bfloat162 b0 = __floats2bfloat162_rn(v.x, v.y);
      __nv_bfloat162 b1 = __floats2bfloat162_rn(v.z, v.w);
      *(__nv_bfloat162*)&xs[r*STR + q*32 + i*4]     = b0;
      *(__nv_bfloat162*)&xs[r*STR + q*32 + i*4 + 2] = b1;
    }
    s += __shfl_xor_sync(FULLM, s, 1);
    s += __shfl_xor_sync(FULLM, s, 2);
    if (!q) xsq_s[r] = s;
  }
  __syncthreads();

  // A fragments for all of K: a[8 ksteps][2 mf][4 regs] = 64 regs, loaded once.
  uint32_t afr[8][2][4];
  {
    unsigned aAddr[2];
    #pragma unroll
    for (int mf=0;mf<2;mf++)
      aAddr[mf] = xs_u32 + ((wm*32 + mf*16 + (lane&15))*STR + (lane>>4)*8)*2;
    #pragma unroll
    for (int kt=0;kt<8;kt++)
      #pragma unroll
      for (int mf=0;mf<2;mf++)
        ldsm_x4(afr[kt][mf][0],afr[kt][mf][1],afr[kt][mf][2],afr[kt][mf][3],
                aAddr[mf] + kt*32);
  }

  // per-thread row sumsq (4 rows per thread: mf2 x h2)
  float xq[4];
  #pragma unroll
  for (int mf=0;mf<2;mf++)
    #pragma unroll
    for (int h=0;h<2;h++)
      xq[mf*2+h] = xsq_s[wm*32 + mf*16 + h*8 + (lane>>2)];

  // B ldmatrix offset within a ring slot
  const unsigned bOff = ((wn*16 + (lane>>4)*8 + (lane&7))*STR + ((lane>>3)&1)*8)*2;

  // packed top-4 per thread per row
  float tv[4][4];
  #pragma unroll
  for (int r=0;r<4;r++)
    #pragma unroll
    for (int j=0;j<4;j++) tv[r][j] = -1e30f;

  int slot = 0;
  int parity = 0;
  for (int chunk=0; chunk<NCHUNK; chunk++){
    // data ready for this slot?
    mbar_wait(mb_u32 + slot*8, parity);
    __syncthreads();   // also proves all warps finished reading slot (chunk+2)%3
    if (chunk+2 < NCHUNK && tid == 0){
      int ns = slot+2; if (ns >= 3) ns -= 3;
      unsigned mb = mb_u32 + ns*8;
      mbar_expect_tx(mb, B_HALF);
      bulk_g2s(ps_u32 + ns*B_HALF, g_pimg + (size_t)(chunk+2)*B_HALF, B_HALF, mb);
    }

    const unsigned bBase = ps_u32 + slot*B_HALF + bOff;

    float acc[2][2][4];
    #pragma unroll
    for (int mf=0;mf<2;mf++)
      #pragma unroll
      for (int nf=0;nf<2;nf++)
        #pragma unroll
        for (int q=0;q<4;q++) acc[mf][nf][q] = 0.f;

    #pragma unroll
    for (int kt=0;kt<8;kt++){
      uint32_t b[4];
      ldsm_x4(b[0],b[1],b[2],b[3], bBase + kt*32);
      #pragma unroll
      for (int mf=0;mf<2;mf++){
        mma_bf16(acc[mf][0], afr[kt][mf][0],afr[kt][mf][1],afr[kt][mf][2],afr[kt][mf][3], b[0], b[1]);
        mma_bf16(acc[mf][1], afr[kt][mf][0],afr[kt][mf][1],afr[kt][mf][2],afr[kt][mf][3], b[2], b[3]);
      }
    }

    // epilogue: scores = (2xp - psq) - xsq ; branchless top-4 of (2xp - psq)
    const int colBase = chunk*BN + wn*16;
    const int cl2 = (lane&3)*2;
    float npq[4];
    {
      float2 v0 = *(const float2*)&npsq_s[colBase + cl2];
      float2 v1 = *(const float2*)&npsq_s[colBase + 8 + cl2];
      npq[0]=v0.x; npq[1]=v0.y; npq[2]=v1.x; npq[3]=v1.y;
    }
    #pragma unroll
    for (int mf=0;mf<2;mf++){
      #pragma unroll
      for (int h=0;h<2;h++){
        const int rl   = mf*2 + h;
        const int grow = blockRow + wm*32 + mf*16 + h*8 + (lane>>2);
        const float xqv = xq[rl];
        float* srow = scores + (size_t)grow*KK;
        #pragma unroll
        for (int nf=0;nf<2;nf++){
          const int col = colBase + nf*8 + cl2;
          float t0 = fmaf(2.f, acc[mf][nf][h*2+0], npq[2*nf]);
          float t1 = fmaf(2.f, acc[mf][nf][h*2+1], npq[2*nf+1]);
          float2 o; o.x = t0 - xqv; o.y = t1 - xqv;
          *(float2*)(srow + col) = o;
          ins4b(tv[rl], packvi(t0, col));
          ins4b(tv[rl], packvi(t1, col+1));
        }
      }
    }
    slot++; if (slot >= 3){ slot -= 3; parity ^= 1; }
  }
  __syncthreads();

  // ---- per-row candidate merge (64 packed cands/row -> top 4) ----
  float* mv = (float*)(smem + A_OFF);              // [64][64] = 16KB
  int4*  c4 = (int4*) (smem + A_OFF + 64*64*4);    // [64]
  #pragma unroll
  for (int mf=0;mf<2;mf++){
    #pragma unroll
    for (int h=0;h<2;h++){
      int r = wm*32 + mf*16 + h*8 + (lane>>2);
      int base = r*64 + wn*16 + (lane&3)*4;
      #pragma unroll
      for (int j=0;j<4;j++) mv[base+j] = tv[mf*2+h][j];
    }
  }
  __syncthreads();
  if (tid < BM){
    float bv[4] = {-1e30f,-1e30f,-1e30f,-1e30f};
    for (int s=0;s<64;s++) ins4b(bv, mv[tid*64+s]);
    int4 o;
    o.x = (int)(__float_as_uint(bv[0]) & 1023u);
    o.y = (int)(__float_as_uint(bv[1]) & 1023u);
    o.z = (int)(__float_as_uint(bv[2]) & 1023u);
    o.w = (int)(__float_as_uint(bv[3]) & 1023u);
    c4[tid] = o;
  }
  __syncthreads();

  // ---- exact fp32 fixup: 8 warps x 8 rows, 4 candidates each ----
  #pragma unroll
  for (int rr=0; rr<8; rr++){
    const int r    = wid*8 + rr;
    const int grow = blockRow + r;
    float4 xv = reinterpret_cast<const float4*>(x + (size_t)grow*DD)[lane];
    const float xqe = xsq_s[r];
    int4 cd = c4[r];
    int cands[4] = {cd.x, cd.y, cd.z, cd.w};
    float bt = 1e30f; int bi = 0x7fffffff;
    #pragma unroll
    for (int j=0;j<4;j++){
      int ci = cands[j];
      float4 pv = reinterpret_cast<const float4*>(p + (size_t)ci*DD)[lane];
      float d = xv.x*pv.x + xv.y*pv.y + xv.z*pv.z + xv.w*pv.w;
      #pragma unroll
      for (int o=16;o;o>>=1) d += __shfl_xor_sync(FULLM, d, o);
      float t = (xqe + g_psq[ci]) - 2.f*d;   // minimize
      if (t < bt || (t == bt && ci < bi)){ bt = t; bi = ci; }
    }
    float4 pv = reinterpret_cast<const float4*>(p + (size_t)bi*DD)[lane];
    reinterpret_cast<float4*>(matched + (size_t)grow*DD)[lane] = pv;
  }
}

// ---------------------------------------------------------------------------
extern "C" void kernel_launch(void* const* d_in, const int* in_sizes, int n_in,
                              void* d_out, int out_size)
{
  const float* x = (const float*)d_in[0];   // [8,4096,128] f32
  const float* p = (const float*)d_in[1];   // [1024,128]   f32
  float* matched = (float*)d_out;                                  // [32768,128]
  float* scores  = (float*)d_out + (size_t)M_TOTAL*DD;             // [32768,1024]

  cudaFuncSetAttribute(gemm_scores_kernel,
                       cudaFuncAttributeMaxDynamicSharedMemorySize, SMEM_BYTES);

  proto_prep_kernel<<<KK/4, 128>>>(p);
  gemm_scores_kernel<<<M_TOTAL/BM, NTHREADS, SMEM_BYTES>>>(x, p, scores, matched);
}

// round 11
// speedup vs baseline: 1.5377x; 1.0034x over previous
#include <cuda_runtime.h>
#include <cuda_bf16.h>
#include <cstdint>

#define FULLM 0xFFFFFFFFu

// Problem dims
#define DD 128
#define KK 1024
#define M_TOTAL 32768

// GEMM tiling
#define BM 64
#define BN 64
#define STR 136            // padded bf16 row stride (272B) for A/B tiles
#define NCHUNK (KK/BN)     // 16
#define NTHREADS 256       // 8 warps: 2 (M) x 4 (N), warptile 32x16

// scores staging tile: 64 rows x 72 floats (stride-72 -> conflict-free)
#define SSTR 72
#define STAGE_BYTES (BM*SSTR*4)         // 18432

// smem layout (bytes)
#define A_OFF    0
#define A_BYTES  STAGE_BYTES            // max(17408 bf16 A-tile, 18432 stage)
#define B_OFF    A_BYTES                // ring of 3
#define B_HALF   (BN*STR*2)             // 17408
#define NPSQ_OFF (B_OFF + 3*B_HALF)     // 70656
#define XSQ_OFF  (NPSQ_OFF + 4096)
#define MBAR_OFF (XSQ_OFF + 256)
#define SMEM_BYTES (MBAR_OFF + 64)      // 75072 (x2 CTAs fits 227KB)

// device scratch: P tiles pre-laid-out as padded [64][STR] bf16 smem images
__device__ __align__(16) unsigned char g_pimg[NCHUNK*B_HALF];
__device__ float g_psq[KK];
__device__ float g_npsq[KK];

__device__ __forceinline__ void ldsm_x4(uint32_t&r0,uint32_t&r1,uint32_t&r2,uint32_t&r3,uint32_t saddr){
  asm volatile("ldmatrix.sync.aligned.m8n8.x4.shared.b16 {%0,%1,%2,%3}, [%4];\n"
    : "=r"(r0),"=r"(r1),"=r"(r2),"=r"(r3) : "r"(saddr));
}

__device__ __forceinline__ void mma_bf16(float c[4],
    uint32_t a0,uint32_t a1,uint32_t a2,uint32_t a3, uint32_t b0, uint32_t b1){
  asm volatile("mma.sync.aligned.m16n8k16.row.col.f32.bf16.bf16.f32 "
    "{%0,%1,%2,%3}, {%4,%5,%6,%7}, {%8,%9}, {%0,%1,%2,%3};\n"
    : "+f"(c[0]),"+f"(c[1]),"+f"(c[2]),"+f"(c[3])
    : "r"(a0),"r"(a1),"r"(a2),"r"(a3),"r"(b0),"r"(b1));
}

__device__ __forceinline__ void mbar_init(unsigned addr, unsigned cnt){
  asm volatile("mbarrier.init.shared.b64 [%0], %1;" :: "r"(addr), "r"(cnt) : "memory");
}
__device__ __forceinline__ void mbar_expect_tx(unsigned addr, unsigned bytes){
  asm volatile("mbarrier.arrive.expect_tx.shared.b64 _, [%0], %1;"
               :: "r"(addr), "r"(bytes) : "memory");
}
__device__ __forceinline__ void bulk_g2s(unsigned sdst, const void* gsrc, unsigned bytes, unsigned mbar){
  asm volatile("cp.async.bulk.shared::cta.global.mbarrier::complete_tx::bytes [%0], [%1], %2, [%3];"
               :: "r"(sdst), "l"(gsrc), "r"(bytes), "r"(mbar) : "memory");
}
__device__ __forceinline__ void mbar_wait(unsigned addr, unsigned parity){
  unsigned done;
  asm volatile("{\n\t.reg .pred p;\n\t"
    "mbarrier.try_wait.parity.acquire.cta.shared::cta.b64 p, [%1], %2;\n\t"
    "selp.b32 %0, 1, 0, p;\n\t}" : "=r"(done) : "r"(addr), "r"(parity) : "memory");
  while (!done){
    asm volatile("{\n\t.reg .pred p;\n\t"
      "mbarrier.try_wait.parity.acquire.cta.shared::cta.b64 p, [%1], %2, 0x989680;\n\t"
      "selp.b32 %0, 1, 0, p;\n\t}" : "=r"(done) : "r"(addr), "r"(parity) : "memory");
  }
}

__device__ __forceinline__ void sts64(unsigned addr, float a, float b){
  asm volatile("st.shared.v2.f32 [%0], {%1,%2};" :: "r"(addr), "f"(a), "f"(b) : "memory");
}
__device__ __forceinline__ void lds128(unsigned addr, float&a,float&b,float&c,float&d){
  asm volatile("ld.shared.v4.f32 {%0,%1,%2,%3}, [%4];" : "=f"(a),"=f"(b),"=f"(c),"=f"(d) : "r"(addr));
}

// branchless sorted-descending top-4 insert: 8 FMNMX, no BSSY/BSYNC.
__device__ __forceinline__ void ins4b(float* tv, float v){
  float m3 = fmaxf(tv[3], v);
  float m2 = fmaxf(tv[2], m3); tv[3] = fminf(tv[2], m3);
  float m1 = fmaxf(tv[1], m2); tv[2] = fminf(tv[1], m2);
  float m0 = fmaxf(tv[0], m1); tv[1] = fminf(tv[0], m1); tv[0] = m0;
}
// pack score value with 10-bit column index in low mantissa bits (1 LOP3)
__device__ __forceinline__ float packvi(float t, int col){
  return __uint_as_float((__float_as_uint(t) & 0xFFFFFC00u) | (unsigned)col);
}

// ---------------------------------------------------------------------------
// Kernel 1: prototypes -> padded bf16 tile image + psq/npsq.  1 warp / row.
// ---------------------------------------------------------------------------
__global__ void __launch_bounds__(128) proto_prep_kernel(const float* __restrict__ p){
  int row  = blockIdx.x*4 + (threadIdx.x>>5);
  int lane = threadIdx.x & 31;
  float4 v = reinterpret_cast<const float4*>(p + (size_t)row*DD)[lane];
  float s = v.x*v.x + v.y*v.y + v.z*v.z + v.w*v.w;
  __nv_bfloat162 b0 = __floats2bfloat162_rn(v.x, v.y);
  __nv_bfloat162 b1 = __floats2bfloat162_rn(v.z, v.w);
  uint2 w; w.x = *(uint32_t*)&b0; w.y = *(uint32_t*)&b1;
  int chunk = row >> 6, r = row & 63;
  *(uint2*)(g_pimg + (size_t)chunk*B_HALF + r*(STR*2) + lane*8) = w;
  #pragma unroll
  for (int o=16;o;o>>=1) s += __shfl_xor_sync(FULLM, s, o);
  if (!lane){ g_psq[row] = s; g_npsq[row] = -s; }
}

// ---------------------------------------------------------------------------
// Kernel 2: fused GEMM (A-in-registers) + staged coalesced scores stores +
// per-value packed top-4 tracking (R9-validated) + exact fixup.  2 CTAs/SM.
// ---------------------------------------------------------------------------
__global__ void __launch_bounds__(NTHREADS,2)
gemm_scores_kernel(const float* __restrict__ x, const float* __restrict__ p,
                   float* __restrict__ scores, float* __restrict__ matched)
{
  extern __shared__ char smem[];
  __nv_bfloat16* xs    = (__nv_bfloat16*)(smem + A_OFF);
  float*         npsq_s= (float*)(smem + NPSQ_OFF);
  float*         xsq_s = (float*)(smem + XSQ_OFF);

  const int tid  = threadIdx.x;
  const int lane = tid & 31;
  const int wid  = tid >> 5;
  const int wm   = wid >> 2;   // 0..1
  const int wn   = wid & 3;    // 0..3
  const int blockRow = blockIdx.x * BM;

  const unsigned smem_u32 = (unsigned)__cvta_generic_to_shared(smem);
  const unsigned xs_u32 = smem_u32 + A_OFF;
  const unsigned ps_u32 = smem_u32 + B_OFF;
  const unsigned mb_u32 = smem_u32 + MBAR_OFF;

  // init mbarriers + kick off first two bulk loads (single thread)
  if (tid == 0){
    mbar_init(mb_u32,      1);
    mbar_init(mb_u32 + 8,  1);
    mbar_init(mb_u32 + 16, 1);
    mbar_expect_tx(mb_u32, B_HALF);
    bulk_g2s(ps_u32, g_pimg, B_HALF, mb_u32);
    mbar_expect_tx(mb_u32 + 8, B_HALF);
    bulk_g2s(ps_u32 + B_HALF, g_pimg + B_HALF, B_HALF, mb_u32 + 8);
  }

  // negated psq -> smem (once)
  #pragma unroll
  for (int k=0;k<4;k++) npsq_s[tid + k*NTHREADS] = g_npsq[tid + k*NTHREADS];

  // x tile fp32 -> bf16 smem + row sumsq (4 threads / row)
  {
    int r = tid >> 2;          // 0..63
    int q = tid & 3;
    const float4* src = (const float4*)(x + (size_t)(blockRow + r)*DD + q*32);
    float s = 0.f;
    #pragma unroll
    for (int i=0;i<8;i++){
      float4 v = src[i];
      s += v.x*v.x + v.y*v.y + v.z*v.z + v.w*v.w;
      __nv_bfloat162 b0 = __floats2bfloat162_rn(v.x, v.y);
      __nv_bfloat162 b1 = __floats2bfloat162_rn(v.z, v.w);
      *(__nv_bfloat162*)&xs[r*STR + q*32 + i*4]     = b0;
      *(__nv_bfloat162*)&xs[r*STR + q*32 + i*4 + 2] = b1;
    }
    s += __shfl_xor_sync(FULLM, s, 1);
    s += __shfl_xor_sync(FULLM, s, 2);
    if (!q) xsq_s[r] = s;
  }
  __syncthreads();

  // A fragments for all of K: a[8 ksteps][2 mf][4 regs] = 64 regs, loaded once.
  uint32_t afr[8][2][4];
  {
    unsigned aAddr[2];
    #pragma unroll
    for (int mf=0;mf<2;mf++)
      aAddr[mf] = xs_u32 + ((wm*32 + mf*16 + (lane&15))*STR + (lane>>4)*8)*2;
    #pragma unroll
    for (int kt=0;kt<8;kt++)
      #pragma unroll
      for (int mf=0;mf<2;mf++)
        ldsm_x4(afr[kt][mf][0],afr[kt][mf][1],afr[kt][mf][2],afr[kt][mf][3],
                aAddr[mf] + kt*32);
  }

  // per-thread row sumsq (4 rows per thread: mf2 x h2)
  float xq[4];
  #pragma unroll
  for (int mf=0;mf<2;mf++)
    #pragma unroll
    for (int h=0;h<2;h++)
      xq[mf*2+h] = xsq_s[wm*32 + mf*16 + h*8 + (lane>>2)];

  // B ldmatrix offset within a ring slot
  const unsigned bOff = ((wn*16 + (lane>>4)*8 + (lane&7))*STR + ((lane>>3)&1)*8)*2;

  // staging addresses (constant per thread)
  unsigned stsA[2][2][2];
  #pragma unroll
  for (int mf=0;mf<2;mf++)
    #pragma unroll
    for (int h=0;h<2;h++)
      #pragma unroll
      for (int nf=0;nf<2;nf++){
        int r = wm*32 + mf*16 + h*8 + (lane>>2);
        int c = wn*16 + nf*8 + (lane&3)*2;
        stsA[mf][h][nf] = smem_u32 + A_OFF + (unsigned)(r*SSTR + c)*4;
      }
  const int rrow0 = wid*8 + (lane>>4);
  const unsigned ldsBase = smem_u32 + A_OFF + (unsigned)(rrow0*SSTR + (lane&15)*4)*4;
  float* gBase = scores + (size_t)(blockRow + rrow0)*KK + (lane&15)*4;

  // packed top-4 per thread per row (per-value inserts, R9-validated)
  float tv[4][4];
  #pragma unroll
  for (int r=0;r<4;r++)
    #pragma unroll
    for (int j=0;j<4;j++) tv[r][j] = -1e30f;

  int slot = 0;
  int parity = 0;
  for (int chunk=0; chunk<NCHUNK; chunk++){
    mbar_wait(mb_u32 + slot*8, parity);
    __syncthreads();   // slot data visible; stage free (prev chunk's reads done)
    if (chunk+2 < NCHUNK && tid == 0){
      int ns = slot+2; if (ns >= 3) ns -= 3;
      unsigned mb = mb_u32 + ns*8;
      mbar_expect_tx(mb, B_HALF);
      bulk_g2s(ps_u32 + ns*B_HALF, g_pimg + (size_t)(chunk+2)*B_HALF, B_HALF, mb);
    }

    const unsigned bBase = ps_u32 + slot*B_HALF + bOff;

    float acc[2][2][4];
    #pragma unroll
    for (int mf=0;mf<2;mf++)
      #pragma unroll
      for (int nf=0;nf<2;nf++)
        #pragma unroll
        for (int q=0;q<4;q++) acc[mf][nf][q] = 0.f;

    #pragma unroll
    for (int kt=0;kt<8;kt++){
      uint32_t b[4];
      ldsm_x4(b[0],b[1],b[2],b[3], bBase + kt*32);
      #pragma unroll
      for (int mf=0;mf<2;mf++){
        mma_bf16(acc[mf][0], afr[kt][mf][0],afr[kt][mf][1],afr[kt][mf][2],afr[kt][mf][3], b[0], b[1]);
        mma_bf16(acc[mf][1], afr[kt][mf][0],afr[kt][mf][1],afr[kt][mf][2],afr[kt][mf][3], b[2], b[3]);
      }
    }

    // epilogue: o = (2xp - psq) - xsq -> stage; per-value packed inserts
    const int colBase = chunk*BN + wn*16;
    const int cl2 = (lane&3)*2;
    float npq[4];
    {
      float2 v0 = *(const float2*)&npsq_s[colBase + cl2];
      float2 v1 = *(const float2*)&npsq_s[colBase + 8 + cl2];
      npq[0]=v0.x; npq[1]=v0.y; npq[2]=v1.x; npq[3]=v1.y;
    }
    #pragma unroll
    for (int mf=0;mf<2;mf++){
      #pragma unroll
      for (int h=0;h<2;h++){
        const int rl = mf*2 + h;
        const float xqv = xq[rl];
        const int c0 = colBase + cl2;
        const int c1 = colBase + 8 + cl2;
        float o00 = fmaf(2.f, acc[mf][0][h*2+0], npq[0]) - xqv;
        float o01 = fmaf(2.f, acc[mf][0][h*2+1], npq[1]) - xqv;
        float o10 = fmaf(2.f, acc[mf][1][h*2+0], npq[2]) - xqv;
        float o11 = fmaf(2.f, acc[mf][1][h*2+1], npq[3]) - xqv;
        sts64(stsA[mf][h][0], o00, o01);
        sts64(stsA[mf][h][1], o10, o11);
        ins4b(tv[rl], packvi(o00, c0));
        ins4b(tv[rl], packvi(o01, c0+1));
        ins4b(tv[rl], packvi(o10, c1));
        ins4b(tv[rl], packvi(o11, c1+1));
      }
    }
    __syncthreads();   // stage complete

    // coalesced store phase: warp streams 8 rows x 256B
    float* gp = gBase + chunk*BN;
    #pragma unroll
    for (int j=0;j<4;j++){
      float a,b,c,d;
      lds128(ldsBase + (unsigned)(j*2*SSTR)*4, a,b,c,d);
      float4 v; v.x=a; v.y=b; v.z=c; v.w=d;
      *(float4*)(gp + (size_t)(j*2)*KK) = v;
    }

    slot++; if (slot >= 3){ slot -= 3; parity ^= 1; }
  }
  __syncthreads();

  // ---- per-row candidate merge (64 packed cands/row -> top 4) ----
  float* mv = (float*)(smem + A_OFF);              // [64][64] = 16KB
  int4*  c4 = (int4*) (smem + A_OFF + 64*64*4);    // [64]
  #pragma unroll
  for (int mf=0;mf<2;mf++){
    #pragma unroll
    for (int h=0;h<2;h++){
      int r = wm*32 + mf*16 + h*8 + (lane>>2);
      int base = r*64 + wn*16 + (lane&3)*4;
      #pragma unroll
      for (int j=0;j<4;j++) mv[base+j] = tv[mf*2+h][j];
    }
  }
  __syncthreads();
  if (tid < BM){
    float bv[4] = {-1e30f,-1e30f,-1e30f,-1e30f};
    for (int s=0;s<64;s++) ins4b(bv, mv[tid*64+s]);
    int4 o;
    o.x = (int)(__float_as_uint(bv[0]) & 1023u);
    o.y = (int)(__float_as_uint(bv[1]) & 1023u);
    o.z = (int)(__float_as_uint(bv[2]) & 1023u);
    o.w = (int)(__float_as_uint(bv[3]) & 1023u);
    c4[tid] = o;
  }
  __syncthreads();

  // ---- exact fp32 fixup: 8 warps x 8 rows, 4 candidates each ----
  #pragma unroll
  for (int rr=0; rr<8; rr++){
    const int r    = wid*8 + rr;
    const int grow = blockRow + r;
    float4 xv = reinterpret_cast<const float4*>(x + (size_t)grow*DD)[lane];
    const float xqe = xsq_s[r];
    int4 cd = c4[r];
    int cands[4] = {cd.x, cd.y, cd.z, cd.w};
    float bt = 1e30f; int bi = 0x7fffffff;
    #pragma unroll
    for (int j=0;j<4;j++){
      int ci = cands[j];
      float4 pv = reinterpret_cast<const float4*>(p + (size_t)ci*DD)[lane];
      float d = xv.x*pv.x + xv.y*pv.y + xv.z*pv.z + xv.w*pv.w;
      #pragma unroll
      for (int o=16;o;o>>=1) d += __shfl_xor_sync(FULLM, d, o);
      float t = (xqe + g_psq[ci]) - 2.f*d;   // minimize
      if (t < bt || (t == bt && ci < bi)){ bt = t; bi = ci; }
    }
    float4 pv = reinterpret_cast<const float4*>(p + (size_t)bi*DD)[lane];
    reinterpret_cast<float4*>(matched + (size_t)grow*DD)[lane] = pv;
  }
}

// ---------------------------------------------------------------------------
extern "C" void kernel_launch(void* const* d_in, const int* in_sizes, int n_in,
                              void* d_out, int out_size)
{
  const float* x = (const float*)d_in[0];   // [8,4096,128] f32
  const float* p = (const float*)d_in[1];   // [1024,128]   f32
  float* matched = (float*)d_out;                                  // [32768,128]
  float* scores  = (float*)d_out + (size_t)M_TOTAL*DD;             // [32768,1024]

  cudaFuncSetAttribute(gemm_scores_kernel,
                       cudaFuncAttributeMaxDynamicSharedMemorySize, SMEM_BYTES);

  proto_prep_kernel<<<KK/4, 128>>>(p);
  gemm_scores_kernel<<<M_TOTAL/BM, NTHREADS, SMEM_BYTES>>>(x, p, scores, matched);
}